// round 4
// baseline (speedup 1.0000x reference)
#include <cuda_runtime.h>
#include <cstdint>

#define THREADS 256
// ---- shared memory layout (bytes) ----
#define WS_OFF    0                       // 32j * 4ic * 4nb * 32lane * float2 = 131072
#define WHL_OFF   131072                  // Wh frags: 4kc*4nb*32*8 = 4096
#define WL2_OFF   (WHL_OFF + 4096)       // Wl frags: 4096
#define XT_OFF    (WL2_OFF + 4096)      // two x tiles, 128 rows * 36 floats
#define XT_STRIDE 36
#define XT_BYTES  (128 * XT_STRIDE * 4)  // 18432
#define SMEM_BYTES (XT_OFF + 2 * XT_BYTES)

static __device__ __forceinline__ uint32_t smem_u32(const void* p) {
    uint32_t a;
    asm("{ .reg .u64 t; cvta.to.shared.u64 t, %1; cvt.u32.u64 %0, t; }" : "=r"(a) : "l"(p));
    return a;
}
static __device__ __forceinline__ float tf32r(float f) {
    float o; asm("cvt.rna.tf32.f32 %0, %1;" : "=f"(o) : "f"(f)); return o;
}

// D += A * B, m16n8k8 tf32. acc fp32, A/B b32(tf32).
static __device__ __forceinline__ void mma8(float* acc, const float* a, float2 b) {
    uint32_t a0 = __float_as_uint(a[0]), a1 = __float_as_uint(a[1]);
    uint32_t a2 = __float_as_uint(a[2]), a3 = __float_as_uint(a[3]);
    uint32_t b0 = __float_as_uint(b.x),  b1 = __float_as_uint(b.y);
    asm volatile(
        "mma.sync.aligned.m16n8k8.row.col.f32.tf32.tf32.f32 "
        "{%0,%1,%2,%3}, {%4,%5,%6,%7}, {%8,%9}, {%0,%1,%2,%3};"
        : "+f"(acc[0]), "+f"(acc[1]), "+f"(acc[2]), "+f"(acc[3])
        : "r"(a0), "r"(a1), "r"(a2), "r"(a3), "r"(b0), "r"(b1));
}

#define CP_ASYNC16(dst, src) \
    asm volatile("cp.async.cg.shared.global [%0], [%1], 16;" :: "r"(dst), "l"(src) : "memory")
#define CP_COMMIT() asm volatile("cp.async.commit_group;" ::: "memory")
#define CP_WAIT1()  asm volatile("cp.async.wait_group 1;" ::: "memory")
#define CP_WAIT0()  asm volatile("cp.async.wait_group 0;" ::: "memory")

extern __shared__ __align__(1024) char smem[];

__global__ void __launch_bounds__(THREADS, 1)
nnode_kernel(const float* __restrict__ x, const float* __restrict__ wlin,
             const float* __restrict__ wnl, float* __restrict__ out, int ntiles) {
    const uint32_t sb = smem_u32(smem);
    const int tid  = threadIdx.x;
    const int wid  = tid >> 5;
    const int lane = tid & 31;
    const int q    = lane & 3;        // threadID in group
    const int g    = lane >> 2;       // group (row within 8)
    const int grid = gridDim.x;

    // ================= build W_nl B-fragments in smem ====================
    // ws[j][ic][nb][lane] = { W_nl[n, i0, j], W_nl[n, i0+4, j] },
    //   n = nb*8 + (lane>>2), i0 = (lane&3) + 8*ic
    {
        float2* ws = reinterpret_cast<float2*>(smem + WS_OFF);
        for (int idx = tid; idx < 16384; idx += THREADS) {
            int j  = idx >> 9;
            int ic = (idx >> 7) & 3;
            int nb = (idx >> 5) & 3;
            int ln = idx & 31;
            int n  = nb * 8 + (ln >> 2);
            int i0 = (ln & 3) + 8 * ic;
            float2 v;
            v.x = tf32r(__ldg(wnl + n * 1024 + i0 * 32 + j));
            v.y = tf32r(__ldg(wnl + n * 1024 + (i0 + 4) * 32 + j));
            ws[idx] = v;
        }
    }
    // ================= build W_lin hi/lo B-fragments =====================
    {
        float2* wh = reinterpret_cast<float2*>(smem + WHL_OFF);
        float2* wl = reinterpret_cast<float2*>(smem + WL2_OFF);
        for (int idx = tid; idx < 512; idx += THREADS) {
            int kc = idx >> 7;
            int nb = (idx >> 5) & 3;
            int ln = idx & 31;
            int n  = nb * 8 + (ln >> 2);
            int i0 = kc * 8 + (ln & 3);
            float w0 = __ldg(wlin + i0 * 32 + n);
            float w1 = __ldg(wlin + (i0 + 4) * 32 + n);
            float h0 = tf32r(w0), h1 = tf32r(w1);
            wh[idx] = make_float2(h0, h1);
            wl[idx] = make_float2(tf32r(w0 - h0), tf32r(w1 - h1));
        }
    }

    // ================= staged x-tile prefetch ============================
    // One tile = 128 rows * 32 floats = 4096 floats = 256 threads * 4 floats * 4 iters.
    const int t0 = blockIdx.x;
    if (t0 < ntiles) {
        const float* src = x + (size_t)t0 * 4096;
        #pragma unroll
        for (int s = 0; s < 4; ++s) {
            int f = (tid + s * THREADS) * 4;     // float index in tile [0, 4096)
            int r = f >> 5, c = f & 31;
            CP_ASYNC16(sb + XT_OFF + (uint32_t)(r * XT_STRIDE + c) * 4, src + f);
        }
    }
    CP_COMMIT();

    const int r0 = wid * 16 + g;     // this thread's first row in tile
    const int r1 = r0 + 8;
    const float2* wsp = reinterpret_cast<const float2*>(smem + WS_OFF) + lane;
    const float2* whp = reinterpret_cast<const float2*>(smem + WHL_OFF) + lane;
    const float2* wlp = reinterpret_cast<const float2*>(smem + WL2_OFF) + lane;

    int buf = 0;
    for (int t = t0; t < ntiles; t += grid) {
        __syncthreads();                       // prior reads of buf^1 done
        int tn = t + grid;
        if (tn < ntiles) {
            const float* src = x + (size_t)tn * 4096;
            uint32_t dst = sb + XT_OFF + (uint32_t)(buf ^ 1) * XT_BYTES;
            #pragma unroll
            for (int s = 0; s < 4; ++s) {
                int f = (tid + s * THREADS) * 4;
                int r = f >> 5, c = f & 31;
                CP_ASYNC16(dst + (uint32_t)(r * XT_STRIDE + c) * 4, src + f);
            }
            CP_COMMIT();
            CP_WAIT1();
        } else {
            CP_WAIT0();
        }
        __syncthreads();                       // current buf visible

        const float* xt  = reinterpret_cast<const float*>(smem + XT_OFF + buf * XT_BYTES);
        const float* xr0 = xt + r0 * XT_STRIDE;
        const float* xr1 = xt + r1 * XT_STRIDE;

        // ---- load X fragments (tf32 hi) + lo residual ----
        float xh[4][4], xl[4][4];
        #pragma unroll
        for (int ic = 0; ic < 4; ++ic) {
            float v0 = xr0[q + 8 * ic];
            float v1 = xr1[q + 8 * ic];
            float v2 = xr0[q + 4 + 8 * ic];
            float v3 = xr1[q + 4 + 8 * ic];
            xh[ic][0] = tf32r(v0); xh[ic][1] = tf32r(v1);
            xh[ic][2] = tf32r(v2); xh[ic][3] = tf32r(v3);
            xl[ic][0] = tf32r(v0 - xh[ic][0]); xl[ic][1] = tf32r(v1 - xh[ic][1]);
            xl[ic][2] = tf32r(v2 - xh[ic][2]); xl[ic][3] = tf32r(v3 - xh[ic][3]);
        }

        float acc[4][4];
        #pragma unroll
        for (int nb = 0; nb < 4; ++nb)
            #pragma unroll
            for (int e = 0; e < 4; ++e) acc[nb][e] = 0.f;

        // ---- linear term: xh@Wh + xl@Wh + xh@Wl (near-exact) ----
        #pragma unroll
        for (int kc = 0; kc < 4; ++kc) {
            #pragma unroll
            for (int nb = 0; nb < 4; ++nb) {
                float2 bh = whp[(kc * 4 + nb) * 32];
                float2 bl = wlp[(kc * 4 + nb) * 32];
                mma8(acc[nb], xh[kc], bh);
                mma8(acc[nb], xl[kc], bh);
                mma8(acc[nb], xh[kc], bl);
            }
        }

        // ---- bilinear term: 32 accumulating K=32 GEMMs ----
        #pragma unroll 4
        for (int j = 0; j < 32; ++j) {
            float xj0 = tf32r(xr0[j]);
            float xj1 = tf32r(xr1[j]);
            const float2* wj = wsp + j * 512;
            #pragma unroll
            for (int ic = 0; ic < 4; ++ic) {
                float a[4];
                a[0] = xh[ic][0] * xj0;   // exact fp32 (tf32*tf32)
                a[1] = xh[ic][1] * xj1;
                a[2] = xh[ic][2] * xj0;
                a[3] = xh[ic][3] * xj1;
                #pragma unroll
                for (int nb = 0; nb < 4; ++nb)
                    mma8(acc[nb], a, wj[(ic * 4 + nb) * 32]);
            }
        }

        // ---- store ----
        float* op0 = out + ((size_t)t * 128 + r0) * 32 + q * 2;
        float* op1 = out + ((size_t)t * 128 + r1) * 32 + q * 2;
        #pragma unroll
        for (int nb = 0; nb < 4; ++nb) {
            *reinterpret_cast<float2*>(op0 + nb * 8) = make_float2(acc[nb][0], acc[nb][1]);
            *reinterpret_cast<float2*>(op1 + nb * 8) = make_float2(acc[nb][2], acc[nb][3]);
        }
        buf ^= 1;
    }
}

extern "C" void kernel_launch(void* const* d_in, const int* in_sizes, int n_in,
                              void* d_out, int out_size) {
    const float* x    = (const float*)d_in[0];
    const float* wlin = (const float*)d_in[1];
    const float* wnl  = (const float*)d_in[2];
    float* out = (float*)d_out;

    int ntiles = in_sizes[0] / 4096;        // rows/128, 4096 tiles for B=524288

    int dev = 0, sms = 148;
    cudaGetDevice(&dev);
    cudaDeviceGetAttribute(&sms, cudaDevAttrMultiProcessorCount, dev);
    if (sms <= 0) sms = 148;
    int grid = sms < ntiles ? sms : ntiles;

    cudaFuncSetAttribute(nnode_kernel, cudaFuncAttributeMaxDynamicSharedMemorySize, SMEM_BYTES);
    nnode_kernel<<<grid, THREADS, SMEM_BYTES>>>(x, wlin, wnl, out, ntiles);
}

// round 5
// speedup vs baseline: 1.4983x; 1.4983x over previous
#include <cuda_runtime.h>
#include <cuda_fp16.h>
#include <cstdint>

#define THREADS 256
// ---- shared memory layout (bytes) ----
#define WS16_OFF  0                       // fp16 W_nl frags: 32j*2kc*4nb*32ln*8B = 65536
#define WHL_OFF   65536                   // W_lin hi tf32 frags: 4kc*4nb*32*8 = 4096
#define WL2_OFF   69632                   // W_lin lo frags: 4096
#define XT_OFF    73728                   // two x tiles, 256 rows * 36 floats
#define XT_STRIDE 36
#define XT_BYTES  (256 * XT_STRIDE * 4)   // 36864
#define SMEM_BYTES (XT_OFF + 2 * XT_BYTES) // 147456

static __device__ __forceinline__ uint32_t smem_u32(const void* p) {
    uint32_t a;
    asm("{ .reg .u64 t; cvta.to.shared.u64 t, %1; cvt.u32.u64 %0, t; }" : "=r"(a) : "l"(p));
    return a;
}
static __device__ __forceinline__ float tf32r(float f) {
    float o; asm("cvt.rna.tf32.f32 %0, %1;" : "=f"(o) : "f"(f)); return o;
}
// splat fp32 -> {h,h} packed fp16x2 in one cvt
static __device__ __forceinline__ uint32_t hsplat(float f) {
    uint32_t d; asm("cvt.rn.f16x2.f32 %0, %1, %1;" : "=r"(d) : "f"(f)); return d;
}
static __device__ __forceinline__ uint32_t hmul2(uint32_t a, uint32_t b) {
    uint32_t d; asm("mul.rn.f16x2 %0, %1, %2;" : "=r"(d) : "r"(a), "r"(b)); return d;
}
static __device__ __forceinline__ uint32_t hpack(float lo, float hi) {
    __half2 h = __floats2half2_rn(lo, hi);            // .x = lo half
    return *reinterpret_cast<uint32_t*>(&h);
}

// tf32 m16n8k8: D += A*B
static __device__ __forceinline__ void mma8(float* acc, const float* a, float2 b) {
    uint32_t a0 = __float_as_uint(a[0]), a1 = __float_as_uint(a[1]);
    uint32_t a2 = __float_as_uint(a[2]), a3 = __float_as_uint(a[3]);
    uint32_t b0 = __float_as_uint(b.x),  b1 = __float_as_uint(b.y);
    asm volatile(
        "mma.sync.aligned.m16n8k8.row.col.f32.tf32.tf32.f32 "
        "{%0,%1,%2,%3}, {%4,%5,%6,%7}, {%8,%9}, {%0,%1,%2,%3};"
        : "+f"(acc[0]), "+f"(acc[1]), "+f"(acc[2]), "+f"(acc[3])
        : "r"(a0), "r"(a1), "r"(a2), "r"(a3), "r"(b0), "r"(b1));
}
// f16 m16n8k16: D += A*B, fp32 accum
static __device__ __forceinline__ void mma16(float* acc, uint32_t a0, uint32_t a1,
                                             uint32_t a2, uint32_t a3,
                                             uint32_t b0, uint32_t b1) {
    asm volatile(
        "mma.sync.aligned.m16n8k16.row.col.f32.f16.f16.f32 "
        "{%0,%1,%2,%3}, {%4,%5,%6,%7}, {%8,%9}, {%0,%1,%2,%3};"
        : "+f"(acc[0]), "+f"(acc[1]), "+f"(acc[2]), "+f"(acc[3])
        : "r"(a0), "r"(a1), "r"(a2), "r"(a3), "r"(b0), "r"(b1));
}

#define CP_ASYNC16(dst, src) \
    asm volatile("cp.async.cg.shared.global [%0], [%1], 16;" :: "r"(dst), "l"(src) : "memory")
#define CP_COMMIT() asm volatile("cp.async.commit_group;" ::: "memory")
#define CP_WAIT1()  asm volatile("cp.async.wait_group 1;" ::: "memory")
#define CP_WAIT0()  asm volatile("cp.async.wait_group 0;" ::: "memory")

extern __shared__ __align__(1024) char smem[];

__global__ void __launch_bounds__(THREADS, 1)
nnode_kernel(const float* __restrict__ x, const float* __restrict__ wlin,
             const float* __restrict__ wnl, float* __restrict__ out, int ntiles) {
    const uint32_t sb = smem_u32(smem);
    const int tid  = threadIdx.x;
    const int wid  = tid >> 5;
    const int lane = tid & 31;
    const int q    = lane & 3;
    const int g    = lane >> 2;
    const int grid = gridDim.x;

    // ========== build fp16 W_nl B-fragments ==========
    // ws16[((j*2+kc)*4+nb)*32 + ln] = uint2{ pack(W[n,k0,j],W[n,k0+1,j]),
    //                                        pack(W[n,k0+8,j],W[n,k0+9,j]) }
    //   n = nb*8 + (ln>>2), k0 = kc*16 + 2*(ln&3);  W index: wnl[n*1024 + i*32 + j]
    {
        uint2* ws = reinterpret_cast<uint2*>(smem + WS16_OFF);
        for (int idx = tid; idx < 8192; idx += THREADS) {
            int j  = idx >> 8;
            int kc = (idx >> 7) & 1;
            int nb = (idx >> 5) & 3;
            int ln = idx & 31;
            int n  = nb * 8 + (ln >> 2);
            int k0 = kc * 16 + 2 * (ln & 3);
            const float* wp = wnl + n * 1024 + j;
            uint2 v;
            v.x = hpack(__ldg(wp + k0 * 32),       __ldg(wp + (k0 + 1) * 32));
            v.y = hpack(__ldg(wp + (k0 + 8) * 32), __ldg(wp + (k0 + 9) * 32));
            ws[idx] = v;
        }
    }
    // ========== W_lin hi/lo tf32 fragments ==========
    {
        float2* wh = reinterpret_cast<float2*>(smem + WHL_OFF);
        float2* wl = reinterpret_cast<float2*>(smem + WL2_OFF);
        for (int idx = tid; idx < 512; idx += THREADS) {
            int kc = idx >> 7;
            int nb = (idx >> 5) & 3;
            int ln = idx & 31;
            int n  = nb * 8 + (ln >> 2);
            int i0 = kc * 8 + (ln & 3);
            float w0 = __ldg(wlin + i0 * 32 + n);
            float w1 = __ldg(wlin + (i0 + 4) * 32 + n);
            float h0 = tf32r(w0), h1 = tf32r(w1);
            wh[idx] = make_float2(h0, h1);
            wl[idx] = make_float2(tf32r(w0 - h0), tf32r(w1 - h1));
        }
    }

    // ========== prefetch first 256-row x tile ==========
    // tile = 256*32 = 8192 floats = 256 thr * 4 floats * 8 iters
    const int t0 = blockIdx.x;
    if (t0 < ntiles) {
        const float* src = x + (size_t)t0 * 8192;
        #pragma unroll
        for (int s = 0; s < 8; ++s) {
            int f = (tid + s * THREADS) * 4;
            int r = f >> 5, c = f & 31;
            CP_ASYNC16(sb + XT_OFF + (uint32_t)(r * XT_STRIDE + c) * 4, src + f);
        }
    }
    CP_COMMIT();

    const int base = wid * 32;              // warp's 32 rows in the 256-row tile
    const int rA = base + g;                // +0, +8, +16, +24 via ridx
    const uint2*  wsp = reinterpret_cast<const uint2*>(smem + WS16_OFF) + lane;
    const float2* whp = reinterpret_cast<const float2*>(smem + WHL_OFF) + lane;
    const float2* wlp = reinterpret_cast<const float2*>(smem + WL2_OFF) + lane;

    int buf = 0;
    for (int t = t0; t < ntiles; t += grid) {
        __syncthreads();
        int tn = t + grid;
        if (tn < ntiles) {
            const float* src = x + (size_t)tn * 8192;
            uint32_t dst = sb + XT_OFF + (uint32_t)(buf ^ 1) * XT_BYTES;
            #pragma unroll
            for (int s = 0; s < 8; ++s) {
                int f = (tid + s * THREADS) * 4;
                int r = f >> 5, c = f & 31;
                CP_ASYNC16(dst + (uint32_t)(r * XT_STRIDE + c) * 4, src + f);
            }
            CP_COMMIT();
            CP_WAIT1();
        } else {
            CP_WAIT0();
        }
        __syncthreads();

        const float* xt = reinterpret_cast<const float*>(smem + XT_OFF + buf * XT_BYTES);

        // ---- packed fp16 X fragments: xp[ridx][kc][half] ----
        // ridx -> row rA + 8*ridx ; half0 = cols {2q,2q+1}+16kc, half1 = +8
        uint32_t xp[4][2][2];
        #pragma unroll
        for (int ridx = 0; ridx < 4; ++ridx) {
            const float* xr = xt + (rA + 8 * ridx) * XT_STRIDE;
            #pragma unroll
            for (int kc = 0; kc < 2; ++kc) {
                float2 lo = *reinterpret_cast<const float2*>(xr + kc * 16 + 2 * q);
                float2 hi = *reinterpret_cast<const float2*>(xr + kc * 16 + 2 * q + 8);
                xp[ridx][kc][0] = hpack(lo.x, lo.y);
                xp[ridx][kc][1] = hpack(hi.x, hi.y);
            }
        }

        float acc[2][4][4];
        #pragma unroll
        for (int f = 0; f < 2; ++f)
            #pragma unroll
            for (int nb = 0; nb < 4; ++nb)
                #pragma unroll
                for (int e = 0; e < 4; ++e) acc[f][nb][e] = 0.f;

        // ---- linear term, tf32 3-mma split (near-exact) ----
        #pragma unroll
        for (int kc = 0; kc < 4; ++kc) {
            float xh0[4], xl0[4], xh1[4], xl1[4];
            {
                const float* pA = xt + (rA +  0) * XT_STRIDE + q + 8 * kc;
                const float* pB = xt + (rA +  8) * XT_STRIDE + q + 8 * kc;
                const float* pC = xt + (rA + 16) * XT_STRIDE + q + 8 * kc;
                const float* pD = xt + (rA + 24) * XT_STRIDE + q + 8 * kc;
                float v0 = pA[0], v1 = pB[0], v2 = pA[4], v3 = pB[4];
                xh0[0]=tf32r(v0); xh0[1]=tf32r(v1); xh0[2]=tf32r(v2); xh0[3]=tf32r(v3);
                xl0[0]=tf32r(v0-xh0[0]); xl0[1]=tf32r(v1-xh0[1]);
                xl0[2]=tf32r(v2-xh0[2]); xl0[3]=tf32r(v3-xh0[3]);
                v0 = pC[0]; v1 = pD[0]; v2 = pC[4]; v3 = pD[4];
                xh1[0]=tf32r(v0); xh1[1]=tf32r(v1); xh1[2]=tf32r(v2); xh1[3]=tf32r(v3);
                xl1[0]=tf32r(v0-xh1[0]); xl1[1]=tf32r(v1-xh1[1]);
                xl1[2]=tf32r(v2-xh1[2]); xl1[3]=tf32r(v3-xh1[3]);
            }
            #pragma unroll
            for (int nb = 0; nb < 4; ++nb) {
                float2 bh = whp[(kc * 4 + nb) * 32];
                float2 bl = wlp[(kc * 4 + nb) * 32];
                mma8(acc[0][nb], xh0, bh);
                mma8(acc[0][nb], xl0, bh);
                mma8(acc[0][nb], xh0, bl);
                mma8(acc[1][nb], xh1, bh);
                mma8(acc[1][nb], xl1, bh);
                mma8(acc[1][nb], xh1, bl);
            }
        }

        // ---- bilinear term: fp16 m16n8k16, B frag reused across 2 M-frags ----
        #pragma unroll 4
        for (int j = 0; j < 32; ++j) {
            uint32_t sA = hsplat(xt[(rA +  0) * XT_STRIDE + j]);
            uint32_t sB = hsplat(xt[(rA +  8) * XT_STRIDE + j]);
            uint32_t sC = hsplat(xt[(rA + 16) * XT_STRIDE + j]);
            uint32_t sD = hsplat(xt[(rA + 24) * XT_STRIDE + j]);
            #pragma unroll
            for (int kc = 0; kc < 2; ++kc) {
                uint32_t a0 = hmul2(xp[0][kc][0], sA);
                uint32_t a1 = hmul2(xp[1][kc][0], sB);
                uint32_t a2 = hmul2(xp[0][kc][1], sA);
                uint32_t a3 = hmul2(xp[1][kc][1], sB);
                uint32_t c0 = hmul2(xp[2][kc][0], sC);
                uint32_t c1 = hmul2(xp[3][kc][0], sD);
                uint32_t c2 = hmul2(xp[2][kc][1], sC);
                uint32_t c3 = hmul2(xp[3][kc][1], sD);
                const uint2* wj = wsp + ((j * 2 + kc) * 4) * 32;
                #pragma unroll
                for (int nb = 0; nb < 4; ++nb) {
                    uint2 bb = wj[nb * 32];
                    mma16(acc[0][nb], a0, a1, a2, a3, bb.x, bb.y);
                    mma16(acc[1][nb], c0, c1, c2, c3, bb.x, bb.y);
                }
            }
        }

        // ---- store ----
        #pragma unroll
        for (int f = 0; f < 2; ++f) {
            float* o0 = out + ((size_t)t * 256 + rA + 16 * f) * 32 + 2 * q;
            float* o1 = o0 + 8 * 32;
            #pragma unroll
            for (int nb = 0; nb < 4; ++nb) {
                *reinterpret_cast<float2*>(o0 + nb * 8) =
                    make_float2(acc[f][nb][0], acc[f][nb][1]);
                *reinterpret_cast<float2*>(o1 + nb * 8) =
                    make_float2(acc[f][nb][2], acc[f][nb][3]);
            }
        }
        buf ^= 1;
    }
}

extern "C" void kernel_launch(void* const* d_in, const int* in_sizes, int n_in,
                              void* d_out, int out_size) {
    const float* x    = (const float*)d_in[0];
    const float* wlin = (const float*)d_in[1];
    const float* wnl  = (const float*)d_in[2];
    float* out = (float*)d_out;

    int ntiles = in_sizes[0] / 8192;        // 256-row tiles; 2048 for B=524288

    int dev = 0, sms = 148;
    cudaGetDevice(&dev);
    cudaDeviceGetAttribute(&sms, cudaDevAttrMultiProcessorCount, dev);
    if (sms <= 0) sms = 148;
    int grid = sms < ntiles ? sms : ntiles;

    cudaFuncSetAttribute(nnode_kernel, cudaFuncAttributeMaxDynamicSharedMemorySize, SMEM_BYTES);
    nnode_kernel<<<grid, THREADS, SMEM_BYTES>>>(x, wlin, wnl, out, ntiles);
}